// round 1
// baseline (speedup 1.0000x reference)
#include <cuda_runtime.h>
#include <cuda_bf16.h>
#include <math_constants.h>

// Problem shape (fixed): B=2, H=16, S=2048, D=128, fp32, mask (B,S) int32 over keys.
#define S_LEN   2048
#define DHEAD   128
#define NHEADS  16
#define BATCH   2
#define TILE_M  64
#define TILE_N  64
#define NTILES  (S_LEN / TILE_N)   // 32
#define THREADS 256

// Shared memory layout (float offsets)
#define Q_OFF   0            // 64*128        = 8192
#define K_OFF   8192         // 2 * 64*128    = 16384
#define V_OFF   24576        // 2 * 64*128    = 16384
#define P_OFF   40960        // 64*68         = 4352
#define PSTR    68
#define MSK_OFF 45312        // 2*64 ints
#define SMEM_FLOATS (45312 + 128)
#define SMEM_BYTES  (SMEM_FLOATS * 4)   // 181760 B

__device__ __forceinline__ unsigned sm_u32(const void* p) {
    return (unsigned)__cvta_generic_to_shared(p);
}
__device__ __forceinline__ void cpa16(unsigned d, const void* s) {
    asm volatile("cp.async.cg.shared.global [%0], [%1], 16;" :: "r"(d), "l"(s));
}
__device__ __forceinline__ void cpa4(unsigned d, const void* s) {
    asm volatile("cp.async.ca.shared.global [%0], [%1], 4;" :: "r"(d), "l"(s));
}
__device__ __forceinline__ void cp_commit() { asm volatile("cp.async.commit_group;"); }
template<int N> __device__ __forceinline__ void cp_wait() {
    asm volatile("cp.async.wait_group %0;" :: "n"(N));
}
__device__ __forceinline__ float ex2f(float x) {
    float y; asm("ex2.approx.ftz.f32 %0, %1;" : "=f"(y) : "f"(x)); return y;
}

// Load one 64x128 fp32 tile (2048 float4 chunks) gmem->smem with XOR swizzle.
// Swizzle: physical chunk = c ^ ((row>>2)&7). Conflict-free writes (lanes cover
// distinct chunks of one row), 2-phase-optimal column reads in the QK loop.
__device__ __forceinline__ void load_tile64(float* dst, const float* src, int tid) {
    float4* d4 = (float4*)dst;
    const float4* s4 = (const float4*)src;
    #pragma unroll
    for (int r = 0; r < 8; r++) {
        int e = r * 256 + tid;
        int n = e >> 5, c = e & 31;
        int cs = c ^ ((n >> 2) & 7);
        cpa16(sm_u32(d4 + n * 32 + cs), s4 + e);
    }
}

__global__ void __launch_bounds__(THREADS, 1)
fa_kernel(const float* __restrict__ q, const float* __restrict__ k,
          const float* __restrict__ v, const int* __restrict__ mask,
          float* __restrict__ out)
{
    extern __shared__ float smem[];
    float* Qs = smem + Q_OFF;
    float* Ps = smem + P_OFF;
    int*   Ms = (int*)(smem + MSK_OFF);

    const int tid = threadIdx.x;
    const int tx  = tid & 15;
    const int ty  = tid >> 4;
    const int bh  = blockIdx.y;
    const int q0  = blockIdx.x * TILE_M;

    const size_t bh_off = (size_t)bh * S_LEN * DHEAD;
    const float* qp = q + bh_off + (size_t)q0 * DHEAD;
    const float* kp = k + bh_off;
    const float* vp = v + bh_off;
    const int*   mp = mask + (bh / NHEADS) * S_LEN;

    // Prefetch: group0 = {Q, K0, V0, mask0}; group1 = {K1, V1, mask1}
    load_tile64(Qs,              qp, tid);
    load_tile64(smem + K_OFF,    kp, tid);
    load_tile64(smem + V_OFF,    vp, tid);
    if (tid < 64) cpa4(sm_u32(Ms + tid), mp + tid);
    cp_commit();
    load_tile64(smem + K_OFF + 8192, kp + TILE_N * DHEAD, tid);
    load_tile64(smem + V_OFF + 8192, vp + TILE_N * DHEAD, tid);
    if (tid < 64) cpa4(sm_u32(Ms + 64 + tid), mp + 64 + tid);
    cp_commit();

    float acc[4][8];
    #pragma unroll
    for (int i = 0; i < 4; i++)
        #pragma unroll
        for (int j2 = 0; j2 < 8; j2++) acc[i][j2] = 0.f;
    float run_m[4], run_l[4];
    #pragma unroll
    for (int i = 0; i < 4; i++) { run_m[i] = -CUDART_INF_F; run_l[i] = 0.f; }

    // scores in log2 domain: p = exp2(s*SCALE*log2e - m)
    const float SCL2E  = 0.08838834764831843f * 1.4426950408889634f;
    const float MASKL2 = -1.4426950408889634e9f;   // -1e9 * log2(e)

    const int xq = ty & 7;                 // loop-invariant swizzle XOR for Q rows 4ty+i
    const int xk = tx & 7;                 // loop-invariant swizzle XOR for K rows 4tx+j
    const float4* Q4r = (const float4*)Qs + (4 * ty) * 32;

    for (int t = 0; t < NTILES; t++) {
        const int cur = t & 1;
        if (t + 1 < NTILES) cp_wait<1>(); else cp_wait<0>();
        __syncthreads();

        // ---- S = Q K^T (64x64, per-thread 4x4) ----
        const float4* K4r = (const float4*)(smem + K_OFF + cur * 8192) + (4 * tx) * 32;
        float s[4][4];
        #pragma unroll
        for (int i = 0; i < 4; i++)
            #pragma unroll
            for (int j = 0; j < 4; j++) s[i][j] = 0.f;

        #pragma unroll 8
        for (int c = 0; c < 32; c++) {
            const float4* qb = Q4r + (c ^ xq);
            const float4* kb = K4r + (c ^ xk);
            float4 qv[4], kv[4];
            #pragma unroll
            for (int i = 0; i < 4; i++) qv[i] = qb[i * 32];
            #pragma unroll
            for (int j = 0; j < 4; j++) kv[j] = kb[j * 32];
            #pragma unroll
            for (int i = 0; i < 4; i++)
                #pragma unroll
                for (int j = 0; j < 4; j++) {
                    s[i][j] = fmaf(qv[i].x, kv[j].x, s[i][j]);
                    s[i][j] = fmaf(qv[i].y, kv[j].y, s[i][j]);
                    s[i][j] = fmaf(qv[i].z, kv[j].z, s[i][j]);
                    s[i][j] = fmaf(qv[i].w, kv[j].w, s[i][j]);
                }
        }

        // ---- online softmax (rows split across 16-lane half-warps) ----
        int mk[4];
        #pragma unroll
        for (int j = 0; j < 4; j++) mk[j] = Ms[cur * 64 + 4 * tx + j];
        float4* P4 = (float4*)Ps;   // row stride 17 float4s
        #pragma unroll
        for (int i = 0; i < 4; i++) {
            float scr[4];
            #pragma unroll
            for (int j = 0; j < 4; j++)
                scr[j] = mk[j] ? s[i][j] * SCL2E : MASKL2;
            float mx = fmaxf(fmaxf(scr[0], scr[1]), fmaxf(scr[2], scr[3]));
            #pragma unroll
            for (int o = 8; o > 0; o >>= 1)
                mx = fmaxf(mx, __shfl_xor_sync(0xffffffffu, mx, o));
            float nm   = fmaxf(run_m[i], mx);
            float corr = ex2f(run_m[i] - nm);    // ex2(-inf)=0 on first tile
            run_m[i] = nm;
            float4 pv;
            pv.x = ex2f(scr[0] - nm); pv.y = ex2f(scr[1] - nm);
            pv.z = ex2f(scr[2] - nm); pv.w = ex2f(scr[3] - nm);
            P4[(4 * ty + i) * 17 + tx] = pv;
            float ls = pv.x + pv.y + pv.z + pv.w;
            #pragma unroll
            for (int o = 8; o > 0; o >>= 1)
                ls += __shfl_xor_sync(0xffffffffu, ls, o);
            run_l[i] = run_l[i] * corr + ls;
            #pragma unroll
            for (int j2 = 0; j2 < 8; j2++) acc[i][j2] *= corr;
        }
        __syncthreads();   // P visible to all before PV

        // ---- O += P V (64x128, per-thread 4x8) ----
        const float4* V4  = (const float4*)(smem + V_OFF + cur * 8192);
        const float4* P4c = (const float4*)Ps + (4 * ty) * 17;
        #pragma unroll 4
        for (int n4 = 0; n4 < 16; n4++) {
            float4 p4[4];
            #pragma unroll
            for (int i = 0; i < 4; i++) p4[i] = P4c[i * 17 + n4];
            #pragma unroll
            for (int dn = 0; dn < 4; dn++) {
                int n  = 4 * n4 + dn;
                int c0 = (2 * tx) ^ ((n >> 2) & 7);
                const float4* vb = V4 + n * 32;
                float4 v0 = vb[c0];
                float4 v1 = vb[c0 ^ 1];
                #pragma unroll
                for (int i = 0; i < 4; i++) {
                    float pi = (dn == 0) ? p4[i].x : (dn == 1) ? p4[i].y
                             : (dn == 2) ? p4[i].z : p4[i].w;
                    acc[i][0] = fmaf(pi, v0.x, acc[i][0]);
                    acc[i][1] = fmaf(pi, v0.y, acc[i][1]);
                    acc[i][2] = fmaf(pi, v0.z, acc[i][2]);
                    acc[i][3] = fmaf(pi, v0.w, acc[i][3]);
                    acc[i][4] = fmaf(pi, v1.x, acc[i][4]);
                    acc[i][5] = fmaf(pi, v1.y, acc[i][5]);
                    acc[i][6] = fmaf(pi, v1.z, acc[i][6]);
                    acc[i][7] = fmaf(pi, v1.w, acc[i][7]);
                }
            }
        }
        __syncthreads();   // everyone done reading K/V[cur] before refilling it

        if (t + 2 < NTILES) {
            load_tile64(smem + K_OFF + cur * 8192, kp + (size_t)(t + 2) * TILE_N * DHEAD, tid);
            load_tile64(smem + V_OFF + cur * 8192, vp + (size_t)(t + 2) * TILE_N * DHEAD, tid);
            if (tid < 64) cpa4(sm_u32(Ms + cur * 64 + tid), mp + (t + 2) * 64 + tid);
            cp_commit();
        }
    }

    // ---- epilogue: O / l ----
    float* op = out + bh_off + (size_t)q0 * DHEAD;
    #pragma unroll
    for (int i = 0; i < 4; i++) {
        float inv = 1.0f / run_l[i];
        float4 r0 = make_float4(acc[i][0] * inv, acc[i][1] * inv,
                                acc[i][2] * inv, acc[i][3] * inv);
        float4 r1 = make_float4(acc[i][4] * inv, acc[i][5] * inv,
                                acc[i][6] * inv, acc[i][7] * inv);
        float4* orow = (float4*)(op + (4 * ty + i) * DHEAD);
        orow[2 * tx]     = r0;
        orow[2 * tx + 1] = r1;
    }
}

extern "C" void kernel_launch(void* const* d_in, const int* in_sizes, int n_in,
                              void* d_out, int out_size) {
    const float* q    = (const float*)d_in[0];
    const float* k    = (const float*)d_in[1];
    const float* v    = (const float*)d_in[2];
    const int*   mask = (const int*)d_in[3];
    float* out = (float*)d_out;

    cudaFuncSetAttribute(fa_kernel, cudaFuncAttributeMaxDynamicSharedMemorySize, SMEM_BYTES);
    dim3 grid(S_LEN / TILE_M, BATCH * NHEADS);
    fa_kernel<<<grid, THREADS, SMEM_BYTES>>>(q, k, v, mask, out);
}